// round 11
// baseline (speedup 1.0000x reference)
#include <cuda_runtime.h>
#include <cuda_fp16.h>
#include <cstdint>

#define HID    128
#define KPAD   2048            // padded K (relations)
#define MROWS  8192            // entity rows per phase (S half = 32 MB)
#define KB     64              // K per pipeline chunk (64 halves = 128 B rows)
#define NCH    (KPAD / KB)     // 32 chunks
#define STG_BYTES 32768        // A(16KB)+B(16KB) per stage
#define NSTAGES   3
#define SMEM_TOT  (NSTAGES * STG_BYTES)

// ---- static device scratch ----
__device__ __half g_S  [MROWS * KPAD]; // phase-active incidence matrix (32 MB)
__device__ __half g_Bt [HID  * KPAD];  // Bt[n][k]: transformed table, transposed
__device__ float  g_Wt [HID * HID];    // W transposed
__device__ float  g_T32[KPAD * HID];   // fp32 T[r][o] before transpose

// ===========================================================================
// helpers
// ===========================================================================
__device__ __forceinline__ uint32_t smem_u32(const void* p) {
    uint32_t a;
    asm("{ .reg .u64 t; cvta.to.shared.u64 t, %1; cvt.u32.u64 %0, t; }"
        : "=r"(a) : "l"(p));
    return a;
}
__device__ __forceinline__ void cp_async16(uint32_t dst, const void* src) {
    asm volatile("cp.async.cg.shared.global [%0], [%1], 16;"
                 :: "r"(dst), "l"(src) : "memory");
}
__device__ __forceinline__ void ldsm_x4(uint32_t& r0, uint32_t& r1,
                                        uint32_t& r2, uint32_t& r3, uint32_t a) {
    asm volatile("ldmatrix.sync.aligned.m8n8.x4.shared.b16 {%0,%1,%2,%3}, [%4];"
                 : "=r"(r0), "=r"(r1), "=r"(r2), "=r"(r3) : "r"(a));
}
__device__ __forceinline__ void mma16816(float* c, const uint32_t* a,
                                         uint32_t b0, uint32_t b1) {
    asm volatile(
        "mma.sync.aligned.m16n8k16.row.col.f32.f16.f16.f32 "
        "{%0,%1,%2,%3}, {%4,%5,%6,%7}, {%8,%9}, {%0,%1,%2,%3};"
        : "+f"(c[0]), "+f"(c[1]), "+f"(c[2]), "+f"(c[3])
        : "r"(a[0]), "r"(a[1]), "r"(a[2]), "r"(a[3]), "r"(b0), "r"(b1));
}
#define SWZ_OFF(row, chunk) (((row) * 128) + ((((chunk) ^ ((row) & 7))) << 4))

// ===========================================================================
// Zero the 32 MB S half with regular STG.128 (write-allocate, L2-resident).
// ===========================================================================
__global__ void __launch_bounds__(256) zeroS_kernel()
{
    const int n16 = (MROWS * KPAD * 2) / 16;
    uint4* p = (uint4*)g_S;
    const uint4 z = make_uint4(0, 0, 0, 0);
    int i = blockIdx.x * blockDim.x + threadIdx.x;
    int stride = gridDim.x * blockDim.x;
    for (; i < n16; i += stride) p[i] = z;
}

// ===========================================================================
// W transpose: Wt[i][o] = W[o][i]
// ===========================================================================
__global__ void __launch_bounds__(256) wtrans_kernel(const float* __restrict__ W)
{
    __shared__ float t[32][33];
    const int tx = threadIdx.x & 31, ty = threadIdx.x >> 5;
    const int bi = (blockIdx.x & 3) * 32;
    const int bo = (blockIdx.x >> 2) * 32;
#pragma unroll
    for (int j = 0; j < 4; j++)
        t[ty + j * 8][tx] = W[(bo + ty + j * 8) * HID + bi + tx];
    __syncthreads();
#pragma unroll
    for (int j = 0; j < 4; j++)
        g_Wt[(bi + ty + j * 8) * HID + bo + tx] = t[tx][ty + j * 8];
}

// ===========================================================================
// Transform: T32[r][o] = b[o] + sum_i x[r][i] * Wt[i][o].  Warp per relation.
// ===========================================================================
__global__ void __launch_bounds__(256) transform_kernel(
    const float* __restrict__ rel_features,
    const float* __restrict__ b,
    int R)
{
    __shared__ float xs[8][HID];
    const int wid  = threadIdx.x >> 5;
    const int lane = threadIdx.x & 31;
    const int r    = blockIdx.x * 8 + wid;
    if (r >= R) return;

    ((float4*)xs[wid])[lane] = ((const float4*)(rel_features + (size_t)r * HID))[lane];
    __syncwarp();

    float4 acc = ((const float4*)b)[lane];
    const float4* __restrict__ Wt4 = (const float4*)g_Wt;
#pragma unroll 8
    for (int i = 0; i < HID; i++) {
        float  xi = xs[wid][i];
        float4 w  = Wt4[i * 32 + lane];
        acc.x = fmaf(xi, w.x, acc.x);
        acc.y = fmaf(xi, w.y, acc.y);
        acc.z = fmaf(xi, w.z, acc.z);
        acc.w = fmaf(xi, w.w, acc.w);
    }
    ((float4*)(g_T32 + (size_t)r * HID))[lane] = acc;
}

// ===========================================================================
// T transpose + f32->f16: Bt[o][r] = (half)T32[r][o]; zero-fills r >= R.
// ===========================================================================
__global__ void __launch_bounds__(256) ttrans_kernel(int R)
{
    __shared__ float t[32][33];
    const int tx = threadIdx.x & 31, ty = threadIdx.x >> 5;
    const int r0 = blockIdx.x * 32;
    const int o0 = blockIdx.y * 32;
#pragma unroll
    for (int j = 0; j < 4; j++) {
        int r = r0 + ty + j * 8;
        t[ty + j * 8][tx] = (r < R) ? g_T32[(size_t)r * HID + o0 + tx] : 0.f;
    }
    __syncthreads();
#pragma unroll
    for (int j = 0; j < 4; j++)
        g_Bt[(size_t)(o0 + ty + j * 8) * KPAD + r0 + tx] =
            __float2half(t[tx][ty + j * 8]);
}

// ===========================================================================
// Phase fill: native packed f16x2 L2 reductions into the 32 MB S half.
// Only entities in [base, base + MROWS) are accumulated this phase.
// ===========================================================================
__device__ __forceinline__ void fact_red(int h, int t, int r, float v, int base)
{
    unsigned hv = (unsigned)__half_as_ushort(__float2half(v));
    unsigned pk = (r & 1) ? (hv << 16) : hv;
    const __half2 v2 = *reinterpret_cast<const __half2*>(&pk);
    const int rp = r & ~1;
    const unsigned tl = (unsigned)(t - base);
    if (tl < (unsigned)MROWS)
        atomicAdd((__half2*)(g_S + (size_t)tl * KPAD + rp), v2);
    const unsigned hl = (unsigned)(h - base);
    if (hl < (unsigned)MROWS)
        atomicAdd((__half2*)(g_S + (size_t)hl * KPAD + rp), v2);
}

__global__ void __launch_bounds__(256) fill_kernel(
    const int* __restrict__ heads,
    const int* __restrict__ tails,
    const int* __restrict__ rels,
    const float* __restrict__ val,
    int E, int base)
{
    const int nq = E >> 2;
    const int i  = blockIdx.x * blockDim.x + threadIdx.x;
    if (i < nq) {
        const int4   h = __ldcs((const int4*)heads + i);
        const int4   t = __ldcs((const int4*)tails + i);
        const int4   r = __ldcs((const int4*)rels  + i);
        const float4 v = __ldcs((const float4*)val + i);
        fact_red(h.x, t.x, r.x, v.x, base);
        fact_red(h.y, t.y, r.y, v.y, base);
        fact_red(h.z, t.z, r.z, v.z, base);
        fact_red(h.w, t.w, r.w, v.w, base);
    } else if (i == nq) {
        for (int f = nq * 4; f < E; f++)
            fact_red(__ldcs(heads + f), __ldcs(tails + f),
                     __ldcs(rels + f), __ldcs(val + f), base);
    }
}

// ===========================================================================
// GEMM: out[base + m][n] = relu(sum_k S[m][k] * Bt[n][k]).
// CTA = 128M x 128N tile, 256 thr / 8 warps, HMMA m16n8k16, 3-stage cp.async.
// ===========================================================================
__global__ void __launch_bounds__(256) gemm_kernel(
    float* __restrict__ out, int num_ent, int base)
{
    extern __shared__ char smem[];
    const uint32_t sb = smem_u32(smem);

    const int tid  = threadIdx.x;
    const int lane = tid & 31;
    const int wid  = tid >> 5;
    const int m0   = blockIdx.x * 128;          // local row within S half
    const int mo   = (wid >> 1) * 32;
    const int no   = (wid & 1) * 64;

    float acc[2][8][4];
#pragma unroll
    for (int i = 0; i < 2; i++)
#pragma unroll
        for (int j = 0; j < 8; j++)
#pragma unroll
            for (int k = 0; k < 4; k++) acc[i][j][k] = 0.f;

    auto load_stage = [&](int s, int buf) {
        const int k0 = s * KB;
        const uint32_t bA = sb + buf * STG_BYTES;
        const uint32_t bB = bA + 16384;
#pragma unroll
        for (int i = 0; i < 4; i++) {
            int idx = tid + i * 256;          // 0..1023
            int row = idx >> 3, c = idx & 7;
            cp_async16(bA + SWZ_OFF(row, c),
                       g_S + (size_t)(m0 + row) * KPAD + k0 + c * 8);
            cp_async16(bB + SWZ_OFF(row, c),
                       g_Bt + (size_t)row * KPAD + k0 + c * 8);
        }
        asm volatile("cp.async.commit_group;" ::: "memory");
    };

    load_stage(0, 0);
    load_stage(1, 1);

    for (int s = 0; s < NCH; s++) {
        if (s + 2 < NCH) {
            load_stage(s + 2, (s + 2) % NSTAGES);
            asm volatile("cp.async.wait_group 2;" ::: "memory");
        } else if (s + 1 < NCH) {
            asm volatile("cp.async.wait_group 1;" ::: "memory");
        } else {
            asm volatile("cp.async.wait_group 0;" ::: "memory");
        }
        __syncthreads();

        const uint32_t bA = sb + (s % NSTAGES) * STG_BYTES;
        const uint32_t bB = bA + 16384;

#pragma unroll
        for (int ks = 0; ks < 4; ks++) {
            uint32_t a[2][4];
#pragma unroll
            for (int im = 0; im < 2; im++) {
                int row   = mo + im * 16 + (lane & 15);
                int chunk = ks * 2 + (lane >> 4);
                ldsm_x4(a[im][0], a[im][1], a[im][2], a[im][3],
                        bA + SWZ_OFF(row, chunk));
            }
            uint32_t br[4][4];
#pragma unroll
            for (int jn = 0; jn < 4; jn++) {
                int nrow  = no + jn * 16 + (lane & 7) + (((lane >> 3) & 1) << 3);
                int chunk = ks * 2 + (lane >> 4);
                ldsm_x4(br[jn][0], br[jn][1], br[jn][2], br[jn][3],
                        bB + SWZ_OFF(nrow, chunk));
            }
#pragma unroll
            for (int im = 0; im < 2; im++)
#pragma unroll
                for (int jn = 0; jn < 4; jn++) {
                    mma16816(acc[im][jn * 2 + 0], a[im], br[jn][0], br[jn][2]);
                    mma16816(acc[im][jn * 2 + 1], a[im], br[jn][1], br[jn][3]);
                }
        }
        __syncthreads();
    }

    // epilogue: ReLU + store (global row = base + local)
#pragma unroll
    for (int im = 0; im < 2; im++) {
        int row0 = base + m0 + mo + im * 16 + (lane >> 2);
#pragma unroll
        for (int j = 0; j < 8; j++) {
            int col = no + j * 8 + (lane & 3) * 2;
            float* c = acc[im][j];
            if (row0 < num_ent) {
                float2 v = make_float2(fmaxf(c[0], 0.f), fmaxf(c[1], 0.f));
                *(float2*)(out + (size_t)row0 * HID + col) = v;
            }
            if (row0 + 8 < num_ent) {
                float2 v = make_float2(fmaxf(c[2], 0.f), fmaxf(c[3], 0.f));
                *(float2*)(out + (size_t)(row0 + 8) * HID + col) = v;
            }
        }
    }
}

// ===========================================================================
// Inputs: 0 local_entity(unused) 1 heads 2 tails 3 rels 4 val
//         5 rel_features[R,128] 6 W[128,128] 7 b[128]  -> out f32 [num_ent,128]
// ===========================================================================
extern "C" void kernel_launch(void* const* d_in, const int* in_sizes, int n_in,
                              void* d_out, int out_size)
{
    const int*   heads = (const int*)  d_in[1];
    const int*   tails = (const int*)  d_in[2];
    const int*   rels  = (const int*)  d_in[3];
    const float* val   = (const float*)d_in[4];
    const float* rel_f = (const float*)d_in[5];
    const float* W     = (const float*)d_in[6];
    const float* b     = (const float*)d_in[7];
    float*       out   = (float*)d_out;

    const int E       = in_sizes[1];
    const int R       = in_sizes[5] / HID;
    const int num_ent = out_size / HID;

    cudaFuncSetAttribute(gemm_kernel,
                         cudaFuncAttributeMaxDynamicSharedMemorySize, SMEM_TOT);

    // B-table build (phase-independent)
    wtrans_kernel<<<16, 256>>>(W);
    transform_kernel<<<(R + 7) / 8, 256>>>(rel_f, b, R);
    {
        dim3 g(KPAD / 32, HID / 32);
        ttrans_kernel<<<g, 256>>>(R);
    }

    // Two entity phases: 32 MB active S stays L2-resident through
    // zero -> fill -> gemm.
    const int nthreads = E / 4 + 1;
    for (int p = 0; p * MROWS < num_ent; p++) {
        const int base = p * MROWS;
        const int rows = min(num_ent - base, MROWS);
        zeroS_kernel<<<2048, 256>>>();
        fill_kernel<<<(nthreads + 255) / 256, 256>>>(heads, tails, rels, val,
                                                     E, base);
        gemm_kernel<<<(rows + 127) / 128, 256, SMEM_TOT>>>(out, num_ent, base);
    }
}

// round 12
// speedup vs baseline: 1.4963x; 1.4963x over previous
#include <cuda_runtime.h>
#include <cuda_fp16.h>
#include <cstdint>

#define HID    128
#define KPAD   2048            // padded K (relations)
#define MAXE   16384           // padded entity rows
#define KB     64              // K per pipeline chunk (64 halves = 128 B rows)
#define NCH    (KPAD / KB)     // 32 chunks
#define STG_BYTES 32768        // A(16KB)+B(16KB) per stage
#define NSTAGES   3
#define SMEM_TOT  (NSTAGES * STG_BYTES)

// ---- static device scratch ----
__device__ __half g_S  [MAXE * KPAD];  // dense incidence-value matrix (64 MB)
__device__ __half g_Bt [HID  * KPAD];  // Bt[n][k]: transformed table, transposed
__device__ float  g_Wt [HID * HID];    // W transposed
__device__ float  g_T32[KPAD * HID];   // fp32 T[r][o] before transpose

// ===========================================================================
// helpers
// ===========================================================================
__device__ __forceinline__ uint32_t smem_u32(const void* p) {
    uint32_t a;
    asm("{ .reg .u64 t; cvta.to.shared.u64 t, %1; cvt.u32.u64 %0, t; }"
        : "=r"(a) : "l"(p));
    return a;
}
__device__ __forceinline__ void cp_async16(uint32_t dst, const void* src) {
    asm volatile("cp.async.cg.shared.global [%0], [%1], 16;"
                 :: "r"(dst), "l"(src) : "memory");
}
__device__ __forceinline__ void ldsm_x4(uint32_t& r0, uint32_t& r1,
                                        uint32_t& r2, uint32_t& r3, uint32_t a) {
    asm volatile("ldmatrix.sync.aligned.m8n8.x4.shared.b16 {%0,%1,%2,%3}, [%4];"
                 : "=r"(r0), "=r"(r1), "=r"(r2), "=r"(r3) : "r"(a));
}
__device__ __forceinline__ void mma16816(float* c, const uint32_t* a,
                                         uint32_t b0, uint32_t b1) {
    asm volatile(
        "mma.sync.aligned.m16n8k16.row.col.f32.f16.f16.f32 "
        "{%0,%1,%2,%3}, {%4,%5,%6,%7}, {%8,%9}, {%0,%1,%2,%3};"
        : "+f"(c[0]), "+f"(c[1]), "+f"(c[2]), "+f"(c[3])
        : "r"(a[0]), "r"(a[1]), "r"(a[2]), "r"(a[3]), "r"(b0), "r"(b1));
}
#define SWZ_OFF(row, chunk) (((row) * 128) + ((((chunk) ^ ((row) & 7))) << 4))

// ===========================================================================
// K1: fused zeroS (blocks 16..) + W transpose (blocks 0..15). Independent.
// ===========================================================================
__global__ void __launch_bounds__(256) zero_wtrans_kernel(
    const float* __restrict__ W)
{
    if (blockIdx.x < 16) {
        __shared__ float t[32][33];
        const int tx = threadIdx.x & 31, ty = threadIdx.x >> 5;
        const int bi = (blockIdx.x & 3) * 32;
        const int bo = (blockIdx.x >> 2) * 32;
#pragma unroll
        for (int j = 0; j < 4; j++)
            t[ty + j * 8][tx] = W[(bo + ty + j * 8) * HID + bi + tx];
        __syncthreads();
#pragma unroll
        for (int j = 0; j < 4; j++)
            g_Wt[(bi + ty + j * 8) * HID + bo + tx] = t[tx][ty + j * 8];
    } else {
        const int n16 = (MAXE * KPAD * 2) / 16;
        uint4* p = (uint4*)g_S;
        const uint4 z = make_uint4(0, 0, 0, 0);
        int i = (blockIdx.x - 16) * blockDim.x + threadIdx.x;
        int stride = (gridDim.x - 16) * blockDim.x;
        for (; i < n16; i += stride) p[i] = z;
    }
}

// ===========================================================================
// K2: Transform: T32[r][o] = b[o] + sum_i x[r][i] * Wt[i][o].  Warp/relation.
// ===========================================================================
__global__ void __launch_bounds__(256) transform_kernel(
    const float* __restrict__ rel_features,
    const float* __restrict__ b,
    int R)
{
    __shared__ float xs[8][HID];
    const int wid  = threadIdx.x >> 5;
    const int lane = threadIdx.x & 31;
    const int r    = blockIdx.x * 8 + wid;
    if (r >= R) return;

    ((float4*)xs[wid])[lane] = ((const float4*)(rel_features + (size_t)r * HID))[lane];
    __syncwarp();

    float4 acc = ((const float4*)b)[lane];
    const float4* __restrict__ Wt4 = (const float4*)g_Wt;
#pragma unroll 8
    for (int i = 0; i < HID; i++) {
        float  xi = xs[wid][i];
        float4 w  = Wt4[i * 32 + lane];
        acc.x = fmaf(xi, w.x, acc.x);
        acc.y = fmaf(xi, w.y, acc.y);
        acc.z = fmaf(xi, w.z, acc.z);
        acc.w = fmaf(xi, w.w, acc.w);
    }
    ((float4*)(g_T32 + (size_t)r * HID))[lane] = acc;
}

// ===========================================================================
// K3: fused fill (blocks 256..) + ttrans (blocks 0..255).
// fill: NO-RETURN red.global.add.noftz.f16x2 into S.
// ttrans: Bt[o][r] = (half)T32[r][o], zero-fill r >= R.
// ===========================================================================
__device__ __forceinline__ void fact_red(int h, int t, int r, float v)
{
    unsigned hv = (unsigned)__half_as_ushort(__float2half(v));
    unsigned pk = (r & 1) ? (hv << 16) : hv;
    const int rp = r & ~1;
    asm volatile("red.global.add.noftz.f16x2 [%0], %1;"
                 :: "l"(g_S + (size_t)t * KPAD + rp), "r"(pk) : "memory");
    asm volatile("red.global.add.noftz.f16x2 [%0], %1;"
                 :: "l"(g_S + (size_t)h * KPAD + rp), "r"(pk) : "memory");
}

__global__ void __launch_bounds__(256) fill_ttrans_kernel(
    const int* __restrict__ heads,
    const int* __restrict__ tails,
    const int* __restrict__ rels,
    const float* __restrict__ val,
    int E, int R)
{
    if (blockIdx.x < 256) {
        // ttrans tile: 64 r-tiles x 4 o-tiles
        __shared__ float t[32][33];
        const int tx = threadIdx.x & 31, ty = threadIdx.x >> 5;
        const int r0 = (blockIdx.x & 63) * 32;
        const int o0 = (blockIdx.x >> 6) * 32;
#pragma unroll
        for (int j = 0; j < 4; j++) {
            int r = r0 + ty + j * 8;
            t[ty + j * 8][tx] = (r < R) ? g_T32[(size_t)r * HID + o0 + tx] : 0.f;
        }
        __syncthreads();
#pragma unroll
        for (int j = 0; j < 4; j++)
            g_Bt[(size_t)(o0 + ty + j * 8) * KPAD + r0 + tx] =
                __float2half(t[tx][ty + j * 8]);
        return;
    }

    const int nq = E >> 2;
    const int i  = (blockIdx.x - 256) * blockDim.x + threadIdx.x;
    if (i < nq) {
        const int4   h = __ldcs((const int4*)heads + i);
        const int4   t = __ldcs((const int4*)tails + i);
        const int4   r = __ldcs((const int4*)rels  + i);
        const float4 v = __ldcs((const float4*)val + i);
        fact_red(h.x, t.x, r.x, v.x);
        fact_red(h.y, t.y, r.y, v.y);
        fact_red(h.z, t.z, r.z, v.z);
        fact_red(h.w, t.w, r.w, v.w);
    } else if (i == nq) {
        for (int f = nq * 4; f < E; f++)
            fact_red(__ldcs(heads + f), __ldcs(tails + f),
                     __ldcs(rels + f), __ldcs(val + f));
    }
}

// ===========================================================================
// K4: GEMM out = relu(S @ Bt^T). CTA = 128M x 128N, 256 thr / 8 warps,
// warp tile 32M x 64N, m16n8k16 HMMA, 3-stage cp.async pipeline.
// ===========================================================================
__global__ void __launch_bounds__(256) gemm_kernel(
    float* __restrict__ out, int num_ent)
{
    extern __shared__ char smem[];
    const uint32_t sb = smem_u32(smem);

    const int tid  = threadIdx.x;
    const int lane = tid & 31;
    const int wid  = tid >> 5;
    const int m0   = blockIdx.x * 128;
    const int mo   = (wid >> 1) * 32;
    const int no   = (wid & 1) * 64;

    float acc[2][8][4];
#pragma unroll
    for (int i = 0; i < 2; i++)
#pragma unroll
        for (int j = 0; j < 8; j++)
#pragma unroll
            for (int k = 0; k < 4; k++) acc[i][j][k] = 0.f;

    auto load_stage = [&](int s, int buf) {
        const int k0 = s * KB;
        const uint32_t bA = sb + buf * STG_BYTES;
        const uint32_t bB = bA + 16384;
#pragma unroll
        for (int i = 0; i < 4; i++) {
            int idx = tid + i * 256;          // 0..1023
            int row = idx >> 3, c = idx & 7;
            cp_async16(bA + SWZ_OFF(row, c),
                       g_S + (size_t)(m0 + row) * KPAD + k0 + c * 8);
            cp_async16(bB + SWZ_OFF(row, c),
                       g_Bt + (size_t)row * KPAD + k0 + c * 8);
        }
        asm volatile("cp.async.commit_group;" ::: "memory");
    };

    load_stage(0, 0);
    load_stage(1, 1);

    for (int s = 0; s < NCH; s++) {
        if (s + 2 < NCH) {
            load_stage(s + 2, (s + 2) % NSTAGES);
            asm volatile("cp.async.wait_group 2;" ::: "memory");
        } else if (s + 1 < NCH) {
            asm volatile("cp.async.wait_group 1;" ::: "memory");
        } else {
            asm volatile("cp.async.wait_group 0;" ::: "memory");
        }
        __syncthreads();

        const uint32_t bA = sb + (s % NSTAGES) * STG_BYTES;
        const uint32_t bB = bA + 16384;

#pragma unroll
        for (int ks = 0; ks < 4; ks++) {
            uint32_t a[2][4];
#pragma unroll
            for (int im = 0; im < 2; im++) {
                int row   = mo + im * 16 + (lane & 15);
                int chunk = ks * 2 + (lane >> 4);
                ldsm_x4(a[im][0], a[im][1], a[im][2], a[im][3],
                        bA + SWZ_OFF(row, chunk));
            }
            uint32_t br[4][4];
#pragma unroll
            for (int jn = 0; jn < 4; jn++) {
                int nrow  = no + jn * 16 + (lane & 7) + (((lane >> 3) & 1) << 3);
                int chunk = ks * 2 + (lane >> 4);
                ldsm_x4(br[jn][0], br[jn][1], br[jn][2], br[jn][3],
                        bB + SWZ_OFF(nrow, chunk));
            }
#pragma unroll
            for (int im = 0; im < 2; im++)
#pragma unroll
                for (int jn = 0; jn < 4; jn++) {
                    mma16816(acc[im][jn * 2 + 0], a[im], br[jn][0], br[jn][2]);
                    mma16816(acc[im][jn * 2 + 1], a[im], br[jn][1], br[jn][3]);
                }
        }
        __syncthreads();
    }

    // epilogue: ReLU + store
#pragma unroll
    for (int im = 0; im < 2; im++) {
        int row0 = m0 + mo + im * 16 + (lane >> 2);
#pragma unroll
        for (int j = 0; j < 8; j++) {
            int col = no + j * 8 + (lane & 3) * 2;
            float* c = acc[im][j];
            if (row0 < num_ent) {
                float2 v = make_float2(fmaxf(c[0], 0.f), fmaxf(c[1], 0.f));
                *(float2*)(out + (size_t)row0 * HID + col) = v;
            }
            if (row0 + 8 < num_ent) {
                float2 v = make_float2(fmaxf(c[2], 0.f), fmaxf(c[3], 0.f));
                *(float2*)(out + (size_t)(row0 + 8) * HID + col) = v;
            }
        }
    }
}

// ===========================================================================
// Inputs: 0 local_entity(unused) 1 heads 2 tails 3 rels 4 val
//         5 rel_features[R,128] 6 W[128,128] 7 b[128]  -> out f32 [num_ent,128]
// ===========================================================================
extern "C" void kernel_launch(void* const* d_in, const int* in_sizes, int n_in,
                              void* d_out, int out_size)
{
    const int*   heads = (const int*)  d_in[1];
    const int*   tails = (const int*)  d_in[2];
    const int*   rels  = (const int*)  d_in[3];
    const float* val   = (const float*)d_in[4];
    const float* rel_f = (const float*)d_in[5];
    const float* W     = (const float*)d_in[6];
    const float* b     = (const float*)d_in[7];
    float*       out   = (float*)d_out;

    const int E       = in_sizes[1];
    const int R       = in_sizes[5] / HID;
    const int num_ent = out_size / HID;
    const int mtiles  = (num_ent + 127) / 128;

    cudaFuncSetAttribute(gemm_kernel,
                         cudaFuncAttributeMaxDynamicSharedMemorySize, SMEM_TOT);

    // K1: zero S (resident STG) fused with W transpose
    zero_wtrans_kernel<<<16 + 2048, 256>>>(W);
    // K2: per-relation linear transform (fp32)
    transform_kernel<<<(R + 7) / 8, 256>>>(rel_f, b, R);
    // K3: fill S via no-return f16x2 RED, fused with T transpose->fp16
    const int fillBlocks = (E / 4 + 1 + 255) / 256;
    fill_ttrans_kernel<<<256 + fillBlocks, 256>>>(heads, tails, rels, val, E, R);
    // K4: tensor-core GEMM + ReLU
    gemm_kernel<<<mtiles, 256, SMEM_TOT>>>(out, num_ent);
}